// round 2
// baseline (speedup 1.0000x reference)
#include <cuda_runtime.h>
#include <cstdint>

#define NP 256
#define NG 1024
#define F  128
#define EPSV 1e-5f

#define TP 32
#define TG 64
#define KC 64

// ---------------- device scratch (static, allocation-free) ----------------
__device__ float2 d_PT[F * NP];   // [f][p] : probe value pre-scaled by (w'_0, w'_1) (class pair)
__device__ float2 d_GT[F * NG];   // [f][g] : gallery transposed, PRE-DUPLICATED (x,x)
__device__ float2 d_A[NP];        // A[p,c] = sum_f w'_c p^2
__device__ float2 d_B[NG];        // B[g,c] = sum_f w'_c g^2
__device__ float2 d_K;            // K[c]   = sum_f W[c,f]*(beta - mu*inv) + b[c]

// ---------------- f32x2 packed helpers ----------------
__device__ __forceinline__ unsigned long long fma2(unsigned long long a,
                                                   unsigned long long b,
                                                   unsigned long long c) {
    unsigned long long d;
    asm("fma.rn.f32x2 %0, %1, %2, %3;" : "=l"(d) : "l"(a), "l"(b), "l"(c));
    return d;
}
__device__ __forceinline__ float2 unpack2(unsigned long long v) {
    float2 r;
    asm("mov.b64 {%0, %1}, %2;" : "=f"(r.x), "=f"(r.y) : "l"(v));
    return r;
}

// ---------------- prep: warp-per-row, pure warp-shuffle reduction ----------------
__global__ void __launch_bounds__(256) prep_kernel(
    const float* __restrict__ probe, const float* __restrict__ gal,
    const float* __restrict__ bnw, const float* __restrict__ bnb,
    const float* __restrict__ bnm, const float* __restrict__ bnv,
    const float* __restrict__ W, const float* __restrict__ bias)
{
    const int lane = threadIdx.x & 31;
    const int warp = threadIdx.x >> 5;
    const int row = blockIdx.x * 8 + warp;   // 0..NP+NG (last = K term)

    if (row < NP) {
        const int p = row;
        float a0 = 0.f, a1 = 0.f;
        #pragma unroll
        for (int i = 0; i < 4; i++) {
            const int f = lane + 32 * i;
            const float inv = bnw[f] * rsqrtf(bnv[f] + EPSV);
            const float w0 = W[f] * inv;
            const float w1 = W[F + f] * inv;
            const float x = probe[p * F + f];
            d_PT[f * NP + p] = make_float2(x * w0, x * w1);
            a0 = fmaf(x * w0, x, a0);
            a1 = fmaf(x * w1, x, a1);
        }
        #pragma unroll
        for (int o = 16; o > 0; o >>= 1) {
            a0 += __shfl_down_sync(0xffffffffu, a0, o);
            a1 += __shfl_down_sync(0xffffffffu, a1, o);
        }
        if (lane == 0) d_A[p] = make_float2(a0, a1);
    } else if (row < NP + NG) {
        const int g = row - NP;
        float a0 = 0.f, a1 = 0.f;
        #pragma unroll
        for (int i = 0; i < 4; i++) {
            const int f = lane + 32 * i;
            const float inv = bnw[f] * rsqrtf(bnv[f] + EPSV);
            const float w0 = W[f] * inv;
            const float w1 = W[F + f] * inv;
            const float x = gal[g * F + f];
            d_GT[f * NG + g] = make_float2(x, x);   // pre-duplicated for f32x2
            a0 = fmaf(w0 * x, x, a0);
            a1 = fmaf(w1 * x, x, a1);
        }
        #pragma unroll
        for (int o = 16; o > 0; o >>= 1) {
            a0 += __shfl_down_sync(0xffffffffu, a0, o);
            a1 += __shfl_down_sync(0xffffffffu, a1, o);
        }
        if (lane == 0) d_B[g] = make_float2(a0, a1);
    } else if (row == NP + NG) {
        float k0 = 0.f, k1 = 0.f;
        #pragma unroll
        for (int i = 0; i < 4; i++) {
            const int f = lane + 32 * i;
            const float inv = bnw[f] * rsqrtf(bnv[f] + EPSV);
            const float off = bnb[f] - bnm[f] * inv;
            k0 = fmaf(W[f], off, k0);
            k1 = fmaf(W[F + f], off, k1);
        }
        #pragma unroll
        for (int o = 16; o > 0; o >>= 1) {
            k0 += __shfl_down_sync(0xffffffffu, k0, o);
            k1 += __shfl_down_sync(0xffffffffu, k1, o);
        }
        if (lane == 0) d_K = make_float2(k0 + bias[0], k1 + bias[1]);
    }
}

// ---------------- main: out = A + B + K - 2*cross ----------------
__global__ void __launch_bounds__(512) cls_kernel(float* __restrict__ out) {
    __shared__ float2 sP[KC][TP];   // 16 KB : class-pair per probe
    __shared__ float2 sG[KC][TG];   // 32 KB : dup-pair per gallery

    const int bp = blockIdx.y * TP;
    const int bg = blockIdx.x * TG;
    const int tid = threadIdx.x;
    const int lane = tid & 31;
    const int warp = tid >> 5;      // 0..15 -> probe pair
    const int tp = warp * 2;
    const int tg = lane * 2;

    unsigned long long acc00 = 0ull, acc01 = 0ull, acc10 = 0ull, acc11 = 0ull;

    for (int k0 = 0; k0 < F; k0 += KC) {
        // Fill sP: 64 rows x 16 float4 = 1024 float4; sG: 64 rows x 32 float4 = 2048 float4.
        #pragma unroll
        for (int i = 0; i < 2; i++) {
            const int idx = tid + i * 512;
            const int r = idx >> 4, c = idx & 15;
            ((float4*)&sP[r][0])[c] =
                ((const float4*)(d_PT + (size_t)(k0 + r) * NP + bp))[c];
        }
        #pragma unroll
        for (int i = 0; i < 4; i++) {
            const int idx = tid + i * 512;
            const int r = idx >> 5, c = idx & 31;
            ((float4*)&sG[r][0])[c] =
                ((const float4*)(d_GT + (size_t)(k0 + r) * NG + bg))[c];
        }
        __syncthreads();

        #pragma unroll 16
        for (int f = 0; f < KC; f++) {
            const ulonglong2 pv = *(const ulonglong2*)&sP[f][tp];  // warp-uniform broadcast
            const ulonglong2 gv = *(const ulonglong2*)&sG[f][tg];  // conflict-free
            acc00 = fma2(pv.x, gv.x, acc00);
            acc01 = fma2(pv.x, gv.y, acc01);
            acc10 = fma2(pv.y, gv.x, acc10);
            acc11 = fma2(pv.y, gv.y, acc11);
        }
        __syncthreads();
    }

    // Epilogue: out[p,g,c] = A[p,c] + B[g,c] + K[c] - 2*cross
    const float2 Kc = d_K;
    const float2 B0 = d_B[bg + tg];
    const float2 B1 = d_B[bg + tg + 1];

    #pragma unroll
    for (int i = 0; i < 2; i++) {
        const int p = bp + tp + i;
        const float2 Ap = d_A[p];
        const float ax = Ap.x + Kc.x;
        const float ay = Ap.y + Kc.y;
        const unsigned long long c0 = (i == 0) ? acc00 : acc10;
        const unsigned long long c1 = (i == 0) ? acc01 : acc11;
        float2 u0 = unpack2(c0);
        float2 u1 = unpack2(c1);
        float4 v;
        v.x = fmaf(-2.0f, u0.x, ax + B0.x);
        v.y = fmaf(-2.0f, u0.y, ay + B0.y);
        v.z = fmaf(-2.0f, u1.x, ax + B1.x);
        v.w = fmaf(-2.0f, u1.y, ay + B1.y);
        *(float4*)(out + ((size_t)p * NG + (bg + tg)) * 2) = v;
    }
}

// ---------------- launch ----------------
extern "C" void kernel_launch(void* const* d_in, const int* in_sizes, int n_in,
                              void* d_out, int out_size) {
    const float* probe = (const float*)d_in[0];
    const float* gal   = (const float*)d_in[1];
    const float* bnw   = (const float*)d_in[2];
    const float* bnb   = (const float*)d_in[3];
    const float* bnm   = (const float*)d_in[4];
    const float* bnv   = (const float*)d_in[5];
    const float* W     = (const float*)d_in[6];
    const float* bias  = (const float*)d_in[7];
    float* out = (float*)d_out;

    prep_kernel<<<(NP + NG + 1 + 7) / 8, 256>>>(probe, gal, bnw, bnb, bnm, bnv, W, bias);
    dim3 grid(NG / TG, NP / TP);   // (16, 8) = 128 blocks
    cls_kernel<<<grid, 512>>>(out);
}

// round 6
// speedup vs baseline: 1.5616x; 1.5616x over previous
#include <cuda_runtime.h>
#include <cstdint>

#define NP 256
#define NG 1024
#define F  128
#define EPSV 1e-5f

#define TP 32
#define TG 64
#define KC 64

// ---------------- f32x2 helpers ----------------
__device__ __forceinline__ unsigned long long fma2(unsigned long long a,
                                                   unsigned long long b,
                                                   unsigned long long c) {
    unsigned long long d;
    asm("fma.rn.f32x2 %0, %1, %2, %3;" : "=l"(d) : "l"(a), "l"(b), "l"(c));
    return d;
}
__device__ __forceinline__ unsigned long long dup2(float x) {
    unsigned long long d;
    asm("mov.b64 %0, {%1, %1};" : "=l"(d) : "f"(x));
    return d;
}
__device__ __forceinline__ float2 unpack2(unsigned long long v) {
    float2 r;
    asm("mov.b64 {%0, %1}, %2;" : "=f"(r.x), "=f"(r.y) : "l"(v));
    return r;
}

// ---------------- single fused kernel ----------------
// out[p,g,c] = A[p,c] + B[g,c] + K[c] - 2 * sum_f (p_f * w'_cf) * g_f
__global__ void __launch_bounds__(256) cls_kernel(
    const float* __restrict__ probe, const float* __restrict__ gal,
    const float* __restrict__ bnw, const float* __restrict__ bnb,
    const float* __restrict__ bnm, const float* __restrict__ bnv,
    const float* __restrict__ W, const float* __restrict__ bias,
    float* __restrict__ out)
{
    // __align__(16): sP's size (65*33*8 = 17160 B) is not a 16-multiple, so without
    // explicit alignment sG can land at offset % 16 == 8 -> float4 reads trap (R5 bug).
    __shared__ __align__(16) float2 sP[KC + 1][TP + 1];  // stride 264 B; 8B reads only
    __shared__ __align__(16) float  sG[KC + 1][TG + 4];  // stride 272 B; float4 reads
    __shared__ float2 sA[TP];
    __shared__ float2 sB[TG];

    const int tid  = threadIdx.x;
    const int lane = tid & 31;
    const int warp = tid >> 5;
    const int bp = blockIdx.y * TP;
    const int bg = blockIdx.x * TG;

    // -------- folded weights (lane f-stripe) + K reduction --------
    float w0r[4], w1r[4];
    float kc0 = 0.f, kc1 = 0.f;
    #pragma unroll
    for (int i = 0; i < 4; i++) {
        const int f = lane + 32 * i;
        const float inv = bnw[f] * rsqrtf(bnv[f] + EPSV);
        const float Wf0 = W[f], Wf1 = W[F + f];
        w0r[i] = Wf0 * inv;
        w1r[i] = Wf1 * inv;
        const float off = bnb[f] - bnm[f] * inv;
        kc0 = fmaf(Wf0, off, kc0);
        kc1 = fmaf(Wf1, off, kc1);
    }
    #pragma unroll
    for (int o = 16; o > 0; o >>= 1) {
        kc0 += __shfl_xor_sync(0xffffffffu, kc0, o);
        kc1 += __shfl_xor_sync(0xffffffffu, kc1, o);
    }
    kc0 += bias[0];
    kc1 += bias[1];

    // -------- thread mapping: 2 probes x 4 gallery x 2 classes --------
    const int ty = tid >> 4, tx = tid & 15;
    const int tp = 2 * ty, tg = 4 * tx;

    unsigned long long a00 = 0, a01 = 0, a02 = 0, a03 = 0;
    unsigned long long a10 = 0, a11 = 0, a12 = 0, a13 = 0;

    float pa0[4], pa1[4];
    float gb0[8], gb1[8];
    #pragma unroll
    for (int k = 0; k < 4; k++) { pa0[k] = 0.f; pa1[k] = 0.f; }
    #pragma unroll
    for (int k = 0; k < 8; k++) { gb0[k] = 0.f; gb1[k] = 0.f; }

    #pragma unroll
    for (int c = 0; c < 2; c++) {
        const int kf = c * KC;

        // ---- load + scale probes (coalesced LDG, fused A partials) ----
        #pragma unroll
        for (int k = 0; k < 4; k++) {
            const int p = warp + 8 * k;
            const float* src = probe + (size_t)(bp + p) * F + kf;
            const float x0 = src[lane];
            const float x1 = src[lane + 32];
            const float s00 = x0 * w0r[2 * c],     s01 = x0 * w1r[2 * c];
            const float s10 = x1 * w0r[2 * c + 1], s11 = x1 * w1r[2 * c + 1];
            sP[lane][p]      = make_float2(s00, s01);
            sP[lane + 32][p] = make_float2(s10, s11);
            pa0[k] = fmaf(s00, x0, fmaf(s10, x1, pa0[k]));
            pa1[k] = fmaf(s01, x0, fmaf(s11, x1, pa1[k]));
        }
        // ---- load gallery (coalesced LDG, fused B partials) ----
        #pragma unroll
        for (int k = 0; k < 8; k++) {
            const int g = warp + 8 * k;
            const float* src = gal + (size_t)(bg + g) * F + kf;
            const float x0 = src[lane];
            const float x1 = src[lane + 32];
            sG[lane][g]      = x0;
            sG[lane + 32][g] = x1;
            gb0[k] = fmaf(w0r[2 * c] * x0, x0, fmaf(w0r[2 * c + 1] * x1, x1, gb0[k]));
            gb1[k] = fmaf(w1r[2 * c] * x0, x0, fmaf(w1r[2 * c + 1] * x1, x1, gb1[k]));
        }
        __syncthreads();

        // ---- FMA mainloop; sP via two aligned 8B loads ----
        unsigned long long Pv0 = *(const unsigned long long*)&sP[0][tp];
        unsigned long long Pv1 = *(const unsigned long long*)&sP[0][tp + 1];
        float4 Gv = *(const float4*)&sG[0][tg];
        #pragma unroll 8
        for (int f = 0; f < KC; f++) {
            const unsigned long long P0n = *(const unsigned long long*)&sP[f + 1][tp];
            const unsigned long long P1n = *(const unsigned long long*)&sP[f + 1][tp + 1];
            const float4 Gn = *(const float4*)&sG[f + 1][tg];
            const unsigned long long g0 = dup2(Gv.x);
            const unsigned long long g1 = dup2(Gv.y);
            const unsigned long long g2 = dup2(Gv.z);
            const unsigned long long g3 = dup2(Gv.w);
            a00 = fma2(Pv0, g0, a00);
            a01 = fma2(Pv0, g1, a01);
            a02 = fma2(Pv0, g2, a02);
            a03 = fma2(Pv0, g3, a03);
            a10 = fma2(Pv1, g0, a10);
            a11 = fma2(Pv1, g1, a11);
            a12 = fma2(Pv1, g2, a12);
            a13 = fma2(Pv1, g3, a13);
            Pv0 = P0n; Pv1 = P1n; Gv = Gn;
        }
        __syncthreads();
    }

    // -------- reduce A/B partials across lanes into smem --------
    #pragma unroll
    for (int k = 0; k < 4; k++) {
        float r0 = pa0[k], r1 = pa1[k];
        #pragma unroll
        for (int o = 16; o > 0; o >>= 1) {
            r0 += __shfl_down_sync(0xffffffffu, r0, o);
            r1 += __shfl_down_sync(0xffffffffu, r1, o);
        }
        if (lane == 0) sA[warp + 8 * k] = make_float2(r0, r1);
    }
    #pragma unroll
    for (int k = 0; k < 8; k++) {
        float r0 = gb0[k], r1 = gb1[k];
        #pragma unroll
        for (int o = 16; o > 0; o >>= 1) {
            r0 += __shfl_down_sync(0xffffffffu, r0, o);
            r1 += __shfl_down_sync(0xffffffffu, r1, o);
        }
        if (lane == 0) sB[warp + 8 * k] = make_float2(r0, r1);
    }
    __syncthreads();

    // -------- epilogue --------
    float2 Bv[4];
    #pragma unroll
    for (int j = 0; j < 4; j++) Bv[j] = sB[tg + j];

    #pragma unroll
    for (int i = 0; i < 2; i++) {
        const float2 Ap = sA[tp + i];
        const float ax = Ap.x + kc0;
        const float ay = Ap.y + kc1;
        const float2 u0 = unpack2(i == 0 ? a00 : a10);
        const float2 u1 = unpack2(i == 0 ? a01 : a11);
        const float2 u2 = unpack2(i == 0 ? a02 : a12);
        const float2 u3 = unpack2(i == 0 ? a03 : a13);
        float4 v0, v1;
        v0.x = fmaf(-2.0f, u0.x, ax + Bv[0].x);
        v0.y = fmaf(-2.0f, u0.y, ay + Bv[0].y);
        v0.z = fmaf(-2.0f, u1.x, ax + Bv[1].x);
        v0.w = fmaf(-2.0f, u1.y, ay + Bv[1].y);
        v1.x = fmaf(-2.0f, u2.x, ax + Bv[2].x);
        v1.y = fmaf(-2.0f, u2.y, ay + Bv[2].y);
        v1.z = fmaf(-2.0f, u3.x, ax + Bv[3].x);
        v1.w = fmaf(-2.0f, u3.y, ay + Bv[3].y);
        float4* dst = (float4*)(out + ((size_t)(bp + tp + i) * NG + bg + tg) * 2);
        dst[0] = v0;
        dst[1] = v1;
    }
}

// ---------------- launch: ONE kernel ----------------
extern "C" void kernel_launch(void* const* d_in, const int* in_sizes, int n_in,
                              void* d_out, int out_size) {
    const float* probe = (const float*)d_in[0];
    const float* gal   = (const float*)d_in[1];
    const float* bnw   = (const float*)d_in[2];
    const float* bnb   = (const float*)d_in[3];
    const float* bnm   = (const float*)d_in[4];
    const float* bnv   = (const float*)d_in[5];
    const float* W     = (const float*)d_in[6];
    const float* bias  = (const float*)d_in[7];
    float* out = (float*)d_out;

    dim3 grid(NG / TG, NP / TP);   // (16, 8) = 128 blocks
    cls_kernel<<<grid, 256>>>(probe, gal, bnw, bnb, bnm, bnv, W, bias, out);
}